// round 5
// baseline (speedup 1.0000x reference)
#include <cuda_runtime.h>

// VectorQuantizer fused: z_e [32,64,32,32] f32, emb [1024,64] f32
// out (f32): z_st [2097152], loss, perplexity, encodings [32768 x 1024]

#define ND 64
#define NDP 32                       // d-pairs
#define NK 1024
#define HW 1024
#define NN 32768
#define ZELEMS 2097152
#define ROWS 64                      // rows per block
#define NBLK (NN / ROWS)             // 512
#define XST 66                       // xs row stride (floats), padded
#define ENCROW 65536                 // floats of enc per block (64 rows)

typedef unsigned long long u64;

__device__ u64    g_embT[NDP * NK];  // [dp][k] = (e[k][2dp], e[k][2dp+1])
__device__ float  g_e2[NK];
__device__ int    g_counts[NK];
__device__ double g_losspart[NBLK];

static __device__ __forceinline__ void upk2(u64 v, float& lo, float& hi) {
    asm("mov.b64 {%0, %1}, %2;" : "=f"(lo), "=f"(hi) : "l"(v));
}
static __device__ __forceinline__ void fma2(u64& acc, u64 a, u64 b) {
    asm("fma.rn.f32x2 %0, %1, %2, %0;" : "+l"(acc) : "l"(a), "l"(b));
}
static __device__ __forceinline__ u64 umin64(u64 a, u64 b) { return a < b ? a : b; }

// ---------------------------------------------------------------------------
// prep: transposed d-pair emb table + e2 + counts. grid 128 x 256
// ---------------------------------------------------------------------------
__global__ void vq_prep(const float* __restrict__ emb) {
    const int t = blockIdx.x * 256 + threadIdx.x;     // 0..32767
    const int dp = t >> 10, k = t & (NK - 1);
    g_embT[t] = ((const u64*)emb)[k * NDP + dp];      // coalesced write

    if (t < NK) {
        g_counts[t] = 0;
        const float* er = emb + t * ND;
        double s = 0.0;
#pragma unroll
        for (int i = 0; i < ND; i++) { double v = (double)er[i]; s += v * v; }
        g_e2[t] = (float)s;
    }
}

// ---------------------------------------------------------------------------
// fused main: argmin + z_st + loss + counts + encodings (zeros + ones)
// block = 64 rows x all 1024 codes; warp w -> rows 8w..8w+7; lane g ->
// codes {ct*128 + g + 32c}. acc packed f32x2 over d-pairs. grid 512 x 256.
// ---------------------------------------------------------------------------
__global__ __launch_bounds__(256, 2) void vq_main(const float* __restrict__ ze,
                                                  float* __restrict__ out) {
    __shared__ float  xs[ROWS * XST];    // [row][d], padded  (16.9 KB)
    __shared__ float  sa[ROWS];          // ||x||^2 per row
    __shared__ float  se2[NK];           // e2 tile (4 KB)
    __shared__ double red[256];

    const int tid  = threadIdx.x;
    const int w    = tid >> 5;
    const int g    = tid & 31;
    const int row0 = blockIdx.x * ROWS;
    const int b    = row0 >> 10;
    const int hw0  = row0 & (HW - 1);

    // stage x tile: xs[r][d] = ze[b][d][hw0+r]  (coalesced global reads)
    const float* zbase = ze + (size_t)b * ND * HW + hw0;
#pragma unroll
    for (int i = 0; i < 16; i++) {
        const int idx = tid + i * 256;
        const int d = idx >> 6, r = idx & 63;
        xs[r * XST + d] = zbase[(size_t)d * HW + r];
    }
#pragma unroll
    for (int i = 0; i < 4; i++) se2[tid + i * 256] = g_e2[tid + i * 256];
    __syncthreads();

    // per-row ||x||^2, fp64 sequential (matches reference-side invariance)
    if (tid < ROWS) {
        const float* xr = xs + tid * XST;
        double s = 0.0;
#pragma unroll
        for (int d = 0; d < ND; d++) { double v = (double)xr[d]; s += v * v; }
        sa[tid] = (float)s;
    }

    // encodings region for this block: 64 rows = 65536 floats, base == 8 mod 16
    float* encrow = out + (size_t)ZELEMS + 2 + (size_t)row0 * NK;
    if (tid == 64) *(float2*)encrow = make_float2(0.0f, 0.0f);               // head
    if (tid == 65) *(float2*)(encrow + ENCROW - 2) = make_float2(0.0f, 0.0f); // tail
    float4* enc4 = (float4*)(encrow + 2);            // 16383 aligned float4 slots
    __syncthreads();

    float a[8];
#pragma unroll
    for (int r = 0; r < 8; r++) a[r] = sa[8 * w + r];

    u64 bestk[8];
#pragma unroll
    for (int r = 0; r < 8; r++) bestk[r] = 0xFFFFFFFFFFFFFFFFULL;

    const float* xw = xs + (8 * w) * XST;
    const float4 z4 = make_float4(0.0f, 0.0f, 0.0f, 0.0f);

    for (int ct = 0; ct < 8; ct++) {
        // interleaved enc zero-fill: drains on DRAM under the fma phase
#pragma unroll
        for (int j = 0; j < 8; j++) {
            const int s = ct * 2048 + j * 256 + tid;
            if (s < 16383) enc4[s] = z4;
        }

        const u64* __restrict__ bq = g_embT + ct * 128 + g;
        u64 acc[8][4];
#pragma unroll
        for (int r = 0; r < 8; r++)
#pragma unroll
            for (int c = 0; c < 4; c++) acc[r][c] = 0ULL;

#pragma unroll 4
        for (int dp = 0; dp < NDP; dp++) {
            u64 bv[4];
#pragma unroll
            for (int c = 0; c < 4; c++) bv[c] = bq[dp * NK + 32 * c];  // coalesced
#pragma unroll
            for (int r = 0; r < 8; r++) {
                const u64 av = *(const u64*)(xw + r * XST + 2 * dp);   // broadcast
#pragma unroll
                for (int c = 0; c < 4; c++) fma2(acc[r][c], av, bv[c]);
            }
        }

        // dist = fl(fl(a+e2) - 2*dot); key keeps lowest-index ties
#pragma unroll
        for (int c = 0; c < 4; c++) {
            const int code = ct * 128 + g + 32 * c;
            const float e2 = se2[code];
#pragma unroll
            for (int r = 0; r < 8; r++) {
                float lo, hi;
                upk2(acc[r][c], lo, hi);
                const float dot  = lo + hi;
                const float dist = fmaf(-2.0f, dot, a[r] + e2);
                const u64 key = ((u64)__float_as_uint(dist) << 32) | (unsigned)code;
                bestk[r] = umin64(bestk[r], key);
            }
        }
    }

    // warp reduce over lanes (each lane saw a disjoint code subset)
#pragma unroll
    for (int off = 16; off > 0; off >>= 1)
#pragma unroll
        for (int r = 0; r < 8; r++)
            bestk[r] = umin64(bestk[r], __shfl_down_sync(0xFFFFFFFFu, bestk[r], off));
    int codes[8];
#pragma unroll
    for (int r = 0; r < 8; r++)
        codes[r] = (int)(__shfl_sync(0xFFFFFFFFu, bestk[r], 0) & 0xFFFFFFFFULL);

    __syncthreads();   // all zero-fill stores in block complete before ones

    // one-hot ones + counts: lane r (r<8) handles row 8w+r
    if (g < 8) {
        const int row = 8 * w + g;
        const int cd  = codes[g];
        encrow[(size_t)row * NK + cd] = 1.0f;
        atomicAdd(&g_counts[cd], 1);
    }

    // z_st + loss: 4 lanes per row, each covers 8 d-pairs
    const int r    = g >> 2;
    const int row  = 8 * w + r;
    const int cd   = codes[r];
    const int dpg  = g & 3;
    float* op = out + (size_t)b * ND * HW + hw0 + row;
    double ls = 0.0;
#pragma unroll
    for (int i = 0; i < 8; i++) {
        const int dp = dpg * 8 + i;
        float x0, x1, e0, e1;
        upk2(*(const u64*)(xs + row * XST + 2 * dp), x0, x1);
        upk2(g_embT[dp * NK + cd], e0, e1);
        const float d0 = e0 - x0, d1 = e1 - x1;
        op[(size_t)(2 * dp) * HW]     = x0 + d0;     // z + (z_q - z)
        op[(size_t)(2 * dp + 1) * HW] = x1 + d1;
        ls += (double)(d0 * d0) + (double)(d1 * d1);
    }
    red[tid] = ls;
    __syncthreads();
    for (int st = 128; st > 0; st >>= 1) {
        if (tid < st) red[tid] += red[tid + st];
        __syncthreads();
    }
    if (tid == 0) g_losspart[blockIdx.x] = red[0];
}

// ---------------------------------------------------------------------------
// finalize: loss + perplexity. 1 x 256
// ---------------------------------------------------------------------------
__global__ void vq_fin(float* __restrict__ out) {
    __shared__ double se[256];
    __shared__ double sl[256];
    const int t = threadIdx.x;
    double ent = 0.0;
#pragma unroll
    for (int i = 0; i < 4; i++) {
        const int k = t + 256 * i;
        const float p = (float)g_counts[k] / (float)NN;
        ent += (double)(p * logf(p + 1e-10f));
    }
    se[t] = ent;
    sl[t] = g_losspart[t] + g_losspart[t + 256];
    __syncthreads();
    for (int st = 128; st > 0; st >>= 1) {
        if (t < st) { se[t] += se[t + st]; sl[t] += sl[t + st]; }
        __syncthreads();
    }
    if (t == 0) {
        const float m = (float)(sl[0] / (double)ZELEMS);  // q_latent == e_latent
        out[ZELEMS]     = m + 0.25f * m;
        out[ZELEMS + 1] = expf(-(float)se[0]);
    }
}

extern "C" void kernel_launch(void* const* d_in, const int* in_sizes, int n_in,
                              void* d_out, int out_size) {
    const float* ze  = (const float*)d_in[0];
    const float* emb = (const float*)d_in[1];
    float*       out = (float*)d_out;

    vq_prep<<<128, 256>>>(emb);
    vq_main<<<NBLK, 256>>>(ze, out);
    vq_fin<<<1, 256>>>(out);
}